// round 9
// baseline (speedup 1.0000x reference)
#include <cuda_runtime.h>
#include <cuda_bf16.h>
#include <cstdint>

// ModalConditionedRPE, GB300 sm_103a. Two kernels + PDL overlap.
// R9 = R8 (LDS.128 operand fetches, proven 19.6us) +
//   (a) warp phase rotation: warp w starts the hp2 loop at (2w)&15 and
//       wraps, de-synchronizing LDS bursts / pipe pressure across warps
//       (attacks the 70% issue ceiling = convoy effect);
//   (b) programmatic dependent launch: main kernel launch overlaps the
//       precompute kernel; griddepcontrol.wait before reading g_P/g_Q.
//
// out[i,j] = b2 + sum_h relu(P[i,h] + Q[j,h]) * W2[h]
//   P[i,h] = x_i*W1[0,h] + y_i*W1[1,h] + s_mean[i]*W1[34,h] + Cmod[h]
//   Q[j,h] = -x_j*W1[0,h] - y_j*W1[1,h] + s_mean[j]*W1[35,h]
// s_mean: jax.image.resize 80->40 linear antialias (4-tap triangle,
// edge-renormalized), mean over batch of 4. (Validated rel_err 7.4e-8.)

#define NPIX 1600
#define HDIM 64
#define PAD  68   // smem row stride in floats: 16B-aligned rows for LDS.128

typedef unsigned long long u64;
union F2u { u64 u; float2 f; };
union F4u { float4 v; u64 d[2]; };

__device__ __forceinline__ u64 add2(u64 a, u64 b) {
    u64 r; asm("add.rn.f32x2 %0, %1, %2;" : "=l"(r) : "l"(a), "l"(b)); return r;
}
__device__ __forceinline__ u64 fma2(u64 a, u64 b, u64 c) {
    u64 r; asm("fma.rn.f32x2 %0, %1, %2, %3;" : "=l"(r) : "l"(a), "l"(b), "l"(c)); return r;
}
__device__ __forceinline__ void stg_cs(float* p, float v) {
    asm volatile("st.global.cs.f32 [%0], %1;" :: "l"(p), "f"(v) : "memory");
}

__device__ float g_P[NPIX * HDIM];
__device__ float g_Q[NPIX * HDIM];

// 4-tap antialiased triangle weights for the 80->40 downsample.
__device__ __forceinline__ void resize_taps(int o, float* w, int& t0) {
    t0 = 2 * o - 1;
    float ww[4] = { 0.25f, 0.75f, 0.75f, 0.25f };
    float s = 0.f;
#pragma unroll
    for (int k = 0; k < 4; k++) {
        int ii = t0 + k;
        if (ii < 0 || ii >= 80) ww[k] = 0.f;
        s += ww[k];
    }
    float inv = 1.f / s;
#pragma unroll
    for (int k = 0; k < 4; k++) w[k] = ww[k] * inv;
}

// Kernel 1: grid 25 x 256. Block covers pixels [64*bid, +64).
__global__ __launch_bounds__(256) void precompute_kernel(
    const float* __restrict__ smap,   // (4,1,80,80)
    const float* __restrict__ me,     // (3,16)
    const float* __restrict__ W1,     // (36,64)
    const float* __restrict__ b1,     // (64)
    const int*   __restrict__ qmod,
    const int*   __restrict__ kmod)
{
    __shared__ float sm[64];
    __shared__ float cm[HDIM];
    const int t  = threadIdx.x;
    const int i0 = blockIdx.x * 64;

    // Phase A: s_mean; t -> (pixel t>>2, batch t&3), shfl-reduce over batch.
    {
        int li = t >> 2, b = t & 3;
        int i  = i0 + li;
        int iy = i / 40, ix = i % 40;
        float wy[4], wx[4]; int ty0, tx0;
        resize_taps(iy, wy, ty0);
        resize_taps(ix, wx, tx0);
        const float* base = smap + b * 6400;
        float s = 0.f;
#pragma unroll
        for (int a = 0; a < 4; a++) {
            if (wy[a] == 0.f) continue;
            int yy = ty0 + a;
            float rowacc = 0.f;
#pragma unroll
            for (int c = 0; c < 4; c++) {
                if (wx[c] == 0.f) continue;
                rowacc += wx[c] * base[yy * 80 + tx0 + c];
            }
            s += wy[a] * rowacc;
        }
        s += __shfl_xor_sync(0xffffffffu, s, 1);
        s += __shfl_xor_sync(0xffffffffu, s, 2);
        if (b == 0) sm[li] = s * 0.25f;
    }
    // Phase B: Cmod
    if (t >= 128 && t < 192) {
        int h = t - 128;
        int q = qmod[0], km = kmod[0];
        float c = b1[h];
#pragma unroll
        for (int kk = 0; kk < 16; kk++) {
            c += me[q  * 16 + kk] * W1[(2  + kk) * HDIM + h];
            c += me[km * 16 + kk] * W1[(18 + kk) * HDIM + h];
        }
        cm[h] = c;
    }
    __syncthreads();

    // Phase C: P/Q rows (coalesced over h).
    for (int p = t; p < 64 * HDIM; p += 256) {
        int r = p >> 6, h = p & 63;
        int i  = i0 + r;
        float x = -0.5f + (float)(i % 40) * (1.0f / 39.0f);
        float y = -0.5f + (float)(i / 40) * (1.0f / 39.0f);
        float w0  = W1[h];
        float w1  = W1[HDIM + h];
        float sv  = sm[r];
        g_P[i * HDIM + h] =  x * w0 + y * w1 + sv * W1[34 * HDIM + h] + cm[h];
        g_Q[i * HDIM + h] = -x * w0 - y * w1 + sv * W1[35 * HDIM + h];
    }
}

// Kernel 2: 64x64 tile / block, 4x4 per thread, packed f32x2 math,
// LDS.128 operand loads, per-warp hp phase rotation.
__global__ __launch_bounds__(256) void rpe_main_kernel(
    const float* __restrict__ W2,   // (64)
    const float* __restrict__ b2,   // (1)
    float*       __restrict__ out)  // (1600,1600)
{
    __shared__ __align__(16) float Ps[64 * PAD];
    __shared__ __align__(16) float Qs[64 * PAD];
    __shared__ __align__(16) float w2s[HDIM];

    const int t   = threadIdx.x;
    const int wid = t >> 5;
    const int bi  = blockIdx.y * 64;
    const int bj  = blockIdx.x * 64;

    // Independent of the precompute kernel: stage W2.
    if (t < HDIM) w2s[t] = W2[t];
    const float bb = b2[0];

    // Wait for the primary (precompute) grid before touching g_P / g_Q.
    asm volatile("griddepcontrol.wait;" ::: "memory");

    // Tile fill with float4: 64 rows x 16 float4 per tile; 4 each thread.
#pragma unroll
    for (int k = t; k < 64 * 16; k += 256) {
        int r = k >> 4, c = k & 15;
        float4 vp = *(const float4*)&g_P[(bi + r) * HDIM + 4 * c];
        float4 vq = *(const float4*)&g_Q[(bj + r) * HDIM + 4 * c];
        *(float4*)&Ps[r * PAD + 4 * c] = vp;
        *(float4*)&Qs[r * PAD + 4 * c] = vq;
    }
    __syncthreads();

    const int tx = t & 15;   // j group (stride 16)
    const int ty = (t >> 4); // i group (stride 16)

    const float* psB = &Ps[ty * PAD];
    const float* qsB = &Qs[tx * PAD];

    u64 acc[4][4];
#pragma unroll
    for (int r = 0; r < 4; r++)
#pragma unroll
        for (int c = 0; c < 4; c++) acc[r][c] = 0ull;

    const int ph0 = (2 * wid) & 15;   // per-warp phase offset

#pragma unroll 4
    for (int k0 = 0; k0 < 16; k0++) {
        const int hp2 = (k0 + ph0) & 15;
        F4u w24; w24.v = *(const float4*)&w2s[4 * hp2];
        F4u a4[4], b4[4];
#pragma unroll
        for (int r = 0; r < 4; r++)
            a4[r].v = *(const float4*)&psB[(16 * r) * PAD + 4 * hp2];
#pragma unroll
        for (int c = 0; c < 4; c++)
            b4[c].v = *(const float4*)&qsB[(16 * c) * PAD + 4 * hp2];

#pragma unroll
        for (int r = 0; r < 4; r++) {
#pragma unroll
            for (int c = 0; c < 4; c++) {
                F2u u0, u1;
                u0.u = add2(a4[r].d[0], b4[c].d[0]);     // FADD2
                u0.f.x = fmaxf(u0.f.x, 0.0f);            // FMNMX
                u0.f.y = fmaxf(u0.f.y, 0.0f);
                acc[r][c] = fma2(u0.u, w24.d[0], acc[r][c]);  // FFMA2
                u1.u = add2(a4[r].d[1], b4[c].d[1]);
                u1.f.x = fmaxf(u1.f.x, 0.0f);
                u1.f.y = fmaxf(u1.f.y, 0.0f);
                acc[r][c] = fma2(u1.u, w24.d[1], acc[r][c]);
            }
        }
    }

#pragma unroll
    for (int r = 0; r < 4; r++) {
        int gi = bi + ty + 16 * r;
#pragma unroll
        for (int c = 0; c < 4; c++) {
            int gj = bj + tx + 16 * c;
            F2u v; v.u = acc[r][c];
            stg_cs(&out[gi * NPIX + gj], v.f.x + v.f.y + bb);
        }
    }
}

// metadata order: h, w, q_mod, k_mod, structure_map, mod_embed, W1, b1, W2, b2
extern "C" void kernel_launch(void* const* d_in, const int* in_sizes, int n_in,
                              void* d_out, int out_size)
{
    const int*   qmod = (const int*)d_in[2];
    const int*   kmod = (const int*)d_in[3];
    const float* smap = (const float*)d_in[4];
    const float* me   = (const float*)d_in[5];
    const float* W1   = (const float*)d_in[6];
    const float* b1   = (const float*)d_in[7];
    const float* W2   = (const float*)d_in[8];
    const float* b2   = (const float*)d_in[9];
    float* out = (float*)d_out;

    precompute_kernel<<<25, 256>>>(smap, me, W1, b1, qmod, kmod);

    // Programmatic dependent launch: overlap main-kernel launch latency with
    // the precompute kernel. The main kernel does griddepcontrol.wait before
    // reading g_P/g_Q; since the primary never triggers early, wait implies
    // full completion + visibility of the primary's stores.
    cudaLaunchAttribute attrs[1];
    attrs[0].id = cudaLaunchAttributeProgrammaticStreamSerialization;
    attrs[0].val.programmaticStreamSerializationAllowed = 1;

    cudaLaunchConfig_t cfg = {};
    cfg.gridDim  = dim3(25, 25);
    cfg.blockDim = dim3(256);
    cfg.dynamicSmemBytes = 0;
    cfg.stream = 0;
    cfg.attrs = attrs;
    cfg.numAttrs = 1;

    cudaLaunchKernelEx(&cfg, rpe_main_kernel, W2, b2, (float*)d_out);
}